// round 3
// baseline (speedup 1.0000x reference)
#include <cuda_runtime.h>
#include <cuda_bf16.h>
#include <math.h>

// Problem constants
#define NN_  32
#define C_   192
#define T_   256
#define V_   25
#define S_   3
#define MID_ 64
#define TV_  6400      // T*V
#define KQK_ 1600      // MID*V
#define D3_  576       // 3*C

// Scratch buffers (device globals; allocation is forbidden)
__device__ float g_qt[NN_ * S_ * T_ * KQK_];   // (n,s,t, c*25+v)
__device__ float g_kt[NN_ * S_ * T_ * KQK_];
__device__ float g_vt[NN_ * S_ * T_ * KQK_];
__device__ float g_att[NN_ * S_ * T_ * T_];    // (n,s,t,q)
__device__ float g_y[NN_ * C_ * TV_];          // (n, cfull, t, v)

// ---------------------------------------------------------------------------
// Kernel 1: QKV projection.  per n: (576,192) @ (192,6400), scatter into
// g_qt/g_kt/g_vt transposed layout (t-major rows of 1600 features).
// grid: (jt=100, dt=9, n=32), block 256
// ---------------------------------------------------------------------------
__global__ __launch_bounds__(256) void k_qkv(const float* __restrict__ x,
                                             const float* __restrict__ w_in,
                                             const float* __restrict__ b_in)
{
    __shared__ float As[16][68];   // [k][m], padded
    __shared__ float Bs[16][64];   // [k][j]

    const int n  = blockIdx.z;
    const int dt = blockIdx.y;     // 0..8 (part = dt/3, s = dt%3)
    const int jt = blockIdx.x;     // 0..99

    const float* A = w_in + dt * 64 * C_;                 // lda = 192
    const float* B = x + (size_t)n * C_ * TV_ + jt * 64;  // ldb = 6400

    const int tid = threadIdx.x;
    const int tx = tid & 15, ty = tid >> 4;

    const int am = tid >> 2;
    const int ak = (tid & 3) << 2;
    const int bk = tid >> 4;
    const int bj = (tid & 15) << 2;

    float acc[4][4] = {};

    for (int k0 = 0; k0 < C_; k0 += 16) {
        float4 av = *reinterpret_cast<const float4*>(A + (size_t)am * C_ + k0 + ak);
        As[ak + 0][am] = av.x;
        As[ak + 1][am] = av.y;
        As[ak + 2][am] = av.z;
        As[ak + 3][am] = av.w;
        *reinterpret_cast<float4*>(&Bs[bk][bj]) =
            *reinterpret_cast<const float4*>(B + (size_t)(k0 + bk) * TV_ + bj);
        __syncthreads();
#pragma unroll
        for (int kk = 0; kk < 16; kk++) {
            float ar[4], br[4];
            *reinterpret_cast<float4*>(ar) = *reinterpret_cast<const float4*>(&As[kk][ty << 2]);
            *reinterpret_cast<float4*>(br) = *reinterpret_cast<const float4*>(&Bs[kk][tx << 2]);
#pragma unroll
            for (int i = 0; i < 4; i++)
#pragma unroll
                for (int j = 0; j < 4; j++)
                    acc[i][j] = fmaf(ar[i], br[j], acc[i][j]);
        }
        __syncthreads();
    }

    // Epilogue: scatter to transposed q/k/v.  Within this 64-row tile,
    // part and s are constant.
    const int part = dt / 3;
    const int s = dt % 3;
    float* dst = (part == 0) ? g_qt : (part == 1) ? g_kt : g_vt;
    const size_t nsbase = ((size_t)(n * 3 + s)) * T_ * KQK_;

#pragma unroll
    for (int i = 0; i < 4; i++) {
        const int c = (ty << 2) + i;                 // 0..63
        const float bias = b_in[dt * 64 + c];
#pragma unroll
        for (int j = 0; j < 4; j++) {
            const int jj = jt * 64 + (tx << 2) + j;  // 0..6399
            const int t = jj / 25, v = jj % 25;
            dst[nsbase + (size_t)t * KQK_ + c * 25 + v] = acc[i][j] + bias;
        }
    }
}

// ---------------------------------------------------------------------------
// Kernel 2: att = tanh( Qt @ Kt^T / 1600 ) per (n,s).  NT GEMM, K=1600.
// grid: (qt=4, tt=4, ns=96)
// ---------------------------------------------------------------------------
__global__ __launch_bounds__(256) void k_att()
{
    __shared__ float As[16][68];
    __shared__ float Bs[16][68];

    const int ns = blockIdx.z;
    const int tt = blockIdx.y;
    const int qt = blockIdx.x;

    const float* A = g_qt + (size_t)ns * T_ * KQK_ + (size_t)tt * 64 * KQK_;
    const float* B = g_kt + (size_t)ns * T_ * KQK_ + (size_t)qt * 64 * KQK_;

    const int tid = threadIdx.x;
    const int tx = tid & 15, ty = tid >> 4;
    const int am = tid >> 2;
    const int ak = (tid & 3) << 2;

    float acc[4][4] = {};

    for (int k0 = 0; k0 < KQK_; k0 += 16) {
        float4 av = *reinterpret_cast<const float4*>(A + (size_t)am * KQK_ + k0 + ak);
        As[ak + 0][am] = av.x;
        As[ak + 1][am] = av.y;
        As[ak + 2][am] = av.z;
        As[ak + 3][am] = av.w;
        float4 bv = *reinterpret_cast<const float4*>(B + (size_t)am * KQK_ + k0 + ak);
        Bs[ak + 0][am] = bv.x;
        Bs[ak + 1][am] = bv.y;
        Bs[ak + 2][am] = bv.z;
        Bs[ak + 3][am] = bv.w;
        __syncthreads();
#pragma unroll
        for (int kk = 0; kk < 16; kk++) {
            float ar[4], br[4];
            *reinterpret_cast<float4*>(ar) = *reinterpret_cast<const float4*>(&As[kk][ty << 2]);
            *reinterpret_cast<float4*>(br) = *reinterpret_cast<const float4*>(&Bs[kk][tx << 2]);
#pragma unroll
            for (int i = 0; i < 4; i++)
#pragma unroll
                for (int j = 0; j < 4; j++)
                    acc[i][j] = fmaf(ar[i], br[j], acc[i][j]);
        }
        __syncthreads();
    }

    float* dst = g_att + (size_t)ns * T_ * T_;
    const float inv = 1.0f / (float)KQK_;
#pragma unroll
    for (int i = 0; i < 4; i++) {
        const int t = tt * 64 + (ty << 2) + i;
#pragma unroll
        for (int j = 0; j < 4; j++) {
            const int q = qt * 64 + (tx << 2) + j;
            dst[(size_t)t * T_ + q] = tanhf(acc[i][j] * inv);
        }
    }
}

// ---------------------------------------------------------------------------
// Kernel 3: Y = att @ Vt per (n,s).  NN GEMM, M=256(t), N=1600(c*25+v), K=256(q).
// Writes back into (n, cfull, t, v) layout for the FF stage.
// grid: (jt=25, tt=4, ns=96)
// ---------------------------------------------------------------------------
__global__ __launch_bounds__(256) void k_av()
{
    __shared__ float As[16][68];
    __shared__ float Bs[16][64];

    const int ns = blockIdx.z;
    const int tt = blockIdx.y;
    const int jt = blockIdx.x;

    const float* A = g_att + (size_t)ns * T_ * T_ + (size_t)tt * 64 * T_;  // lda=256
    const float* B = g_vt + (size_t)ns * T_ * KQK_ + jt * 64;              // ldb=1600

    const int tid = threadIdx.x;
    const int tx = tid & 15, ty = tid >> 4;
    const int am = tid >> 2;
    const int ak = (tid & 3) << 2;
    const int bk = tid >> 4;
    const int bj = (tid & 15) << 2;

    float acc[4][4] = {};

    for (int k0 = 0; k0 < T_; k0 += 16) {
        float4 av = *reinterpret_cast<const float4*>(A + (size_t)am * T_ + k0 + ak);
        As[ak + 0][am] = av.x;
        As[ak + 1][am] = av.y;
        As[ak + 2][am] = av.z;
        As[ak + 3][am] = av.w;
        *reinterpret_cast<float4*>(&Bs[bk][bj]) =
            *reinterpret_cast<const float4*>(B + (size_t)(k0 + bk) * KQK_ + bj);
        __syncthreads();
#pragma unroll
        for (int kk = 0; kk < 16; kk++) {
            float ar[4], br[4];
            *reinterpret_cast<float4*>(ar) = *reinterpret_cast<const float4*>(&As[kk][ty << 2]);
            *reinterpret_cast<float4*>(br) = *reinterpret_cast<const float4*>(&Bs[kk][tx << 2]);
#pragma unroll
            for (int i = 0; i < 4; i++)
#pragma unroll
                for (int j = 0; j < 4; j++)
                    acc[i][j] = fmaf(ar[i], br[j], acc[i][j]);
        }
        __syncthreads();
    }

    const int n = ns / 3;
    const int s = ns % 3;
#pragma unroll
    for (int i = 0; i < 4; i++) {
        const int t = tt * 64 + (ty << 2) + i;
#pragma unroll
        for (int j = 0; j < 4; j++) {
            const int jj = jt * 64 + (tx << 2) + j;  // c*25+v
            const int c = jj / 25, v = jj % 25;
            g_y[(((size_t)n * C_ + s * MID_ + c) * T_ + t) * V_ + v] = acc[i][j];
        }
    }
}

// ---------------------------------------------------------------------------
// Kernel 4: FF + BatchNorm + residual + LeakyReLU.
// per n: (192,192) @ (192,6400), epilogue fused.
// grid: (jt=100, dt=3, n=32)
// ---------------------------------------------------------------------------
__global__ __launch_bounds__(256) void k_ff(const float* __restrict__ x,
                                            const float* __restrict__ w_ff,
                                            const float* __restrict__ b_ff,
                                            const float* __restrict__ bn_gamma,
                                            const float* __restrict__ bn_beta,
                                            const float* __restrict__ bn_mean,
                                            const float* __restrict__ bn_var,
                                            float* __restrict__ out)
{
    __shared__ float As[16][68];
    __shared__ float Bs[16][64];

    const int n  = blockIdx.z;
    const int dt = blockIdx.y;
    const int jt = blockIdx.x;

    const float* A = w_ff + dt * 64 * C_;                   // lda = 192
    const float* B = g_y + (size_t)n * C_ * TV_ + jt * 64;  // ldb = 6400

    const int tid = threadIdx.x;
    const int tx = tid & 15, ty = tid >> 4;
    const int am = tid >> 2;
    const int ak = (tid & 3) << 2;
    const int bk = tid >> 4;
    const int bj = (tid & 15) << 2;

    float acc[4][4] = {};

    for (int k0 = 0; k0 < C_; k0 += 16) {
        float4 av = *reinterpret_cast<const float4*>(A + (size_t)am * C_ + k0 + ak);
        As[ak + 0][am] = av.x;
        As[ak + 1][am] = av.y;
        As[ak + 2][am] = av.z;
        As[ak + 3][am] = av.w;
        *reinterpret_cast<float4*>(&Bs[bk][bj]) =
            *reinterpret_cast<const float4*>(B + (size_t)(k0 + bk) * TV_ + bj);
        __syncthreads();
#pragma unroll
        for (int kk = 0; kk < 16; kk++) {
            float ar[4], br[4];
            *reinterpret_cast<float4*>(ar) = *reinterpret_cast<const float4*>(&As[kk][ty << 2]);
            *reinterpret_cast<float4*>(br) = *reinterpret_cast<const float4*>(&Bs[kk][tx << 2]);
#pragma unroll
            for (int i = 0; i < 4; i++)
#pragma unroll
                for (int j = 0; j < 4; j++)
                    acc[i][j] = fmaf(ar[i], br[j], acc[i][j]);
        }
        __syncthreads();
    }

#pragma unroll
    for (int i = 0; i < 4; i++) {
        const int d = dt * 64 + (ty << 2) + i;
        const float inv = bn_gamma[d] * rsqrtf(bn_var[d] + 1e-5f);
        const float mean = bn_mean[d];
        const float beta = bn_beta[d];
        const float bias = b_ff[d];
#pragma unroll
        for (int j = 0; j < 4; j++) {
            const int jj = jt * 64 + (tx << 2) + j;
            const size_t idx = (size_t)n * C_ * TV_ + (size_t)d * TV_ + jj;
            float o = acc[i][j] + bias;
            o = (o - mean) * inv + beta;
            float z = x[idx] + o;
            out[idx] = (z >= 0.0f) ? z : 0.1f * z;
        }
    }
}

// ---------------------------------------------------------------------------
extern "C" void kernel_launch(void* const* d_in, const int* in_sizes, int n_in,
                              void* d_out, int out_size)
{
    const float* x        = (const float*)d_in[0];
    const float* w_in     = (const float*)d_in[1];
    const float* b_in     = (const float*)d_in[2];
    const float* w_ff     = (const float*)d_in[3];
    const float* b_ff     = (const float*)d_in[4];
    const float* bn_gamma = (const float*)d_in[5];
    const float* bn_beta  = (const float*)d_in[6];
    const float* bn_mean  = (const float*)d_in[7];
    const float* bn_var   = (const float*)d_in[8];
    float* out = (float*)d_out;

    k_qkv<<<dim3(100, 9, 32), 256>>>(x, w_in, b_in);
    k_att<<<dim3(4, 4, 96), 256>>>();
    k_av <<<dim3(25, 4, 96), 256>>>();
    k_ff <<<dim3(100, 3, 32), 256>>>(x, w_ff, b_ff, bn_gamma, bn_beta,
                                     bn_mean, bn_var, out);
}

// round 5
// speedup vs baseline: 2.4340x; 2.4340x over previous
#include <cuda_runtime.h>
#include <cstdint>
#include <math.h>

#define C_   192
#define T_   256
#define V_   25
#define TV_  6400
#define KQK_ 1600

// Scratch (device globals; allocation forbidden)
__device__ float g_qt[32u*3*256*1600];   // [ns][t][v*64+c]
__device__ float g_kt[32u*3*256*1600];   // [ns][q][v*64+c]
__device__ float g_vt[32u*3*1600*256];   // [ns][v*64+c][q]
__device__ float g_att[32u*3*256*256];   // [ns][t][q]
__device__ float g_y[32u*6400*192];      // [n][t*25+v][c_full]

__device__ __forceinline__ float to_tf32(float x) {
    float y; asm("cvt.rna.tf32.f32 %0, %1;" : "=f"(y) : "f"(x)); return y;
}
__device__ __forceinline__ float4 tf32x4(float4 v) {
    v.x = to_tf32(v.x); v.y = to_tf32(v.y); v.z = to_tf32(v.z); v.w = to_tf32(v.w);
    return v;
}

#define MMA(d, a, b)                                                          \
    asm volatile(                                                             \
        "mma.sync.aligned.m16n8k8.row.col.f32.tf32.tf32.f32 "                 \
        "{%0,%1,%2,%3},{%4,%5,%6,%7},{%8,%9},{%0,%1,%2,%3};"                  \
        : "+f"((d)[0]), "+f"((d)[1]), "+f"((d)[2]), "+f"((d)[3])              \
        : "r"((a)[0]), "r"((a)[1]), "r"((a)[2]), "r"((a)[3]),                 \
          "r"((b)[0]), "r"((b)[1]))

#define MKS 36     // [m][k] row stride (words); bank = (4g+tig)%32, conflict-free
#define KMS 136    // [k][m] row stride; bank = (8*tig+g)%32, conflict-free

// A,B in [m][k]/[n][k] layout, stride 36.  acc[2][8][4], warp tile 32x64.
__device__ __forceinline__ void compute_mk(const float* __restrict__ As,
                                           const float* __restrict__ Bs,
                                           float acc[2][8][4], int m0, int g, int tig)
{
#pragma unroll
    for (int ks = 0; ks < 4; ks++) {
        const int k = ks * 8;
        uint32_t a[2][4];
#pragma unroll
        for (int mf = 0; mf < 2; mf++) {
            const float* ap = As + (m0 + mf * 16 + g) * MKS + k + tig;
            a[mf][0] = __float_as_uint(ap[0]);
            a[mf][1] = __float_as_uint(ap[8 * MKS]);
            a[mf][2] = __float_as_uint(ap[4]);
            a[mf][3] = __float_as_uint(ap[8 * MKS + 4]);
        }
#pragma unroll
        for (int nf = 0; nf < 8; nf++) {
            uint32_t b[2];
            const float* bp = Bs + (nf * 8 + g) * MKS + k + tig;
            b[0] = __float_as_uint(bp[0]);
            b[1] = __float_as_uint(bp[4]);
            MMA(acc[0][nf], a[0], b);
            MMA(acc[1][nf], a[1], b);
        }
    }
}

// A in [k][m] layout stride 136 (for transposed staging); B in [n][k].
__device__ __forceinline__ void compute_km(const float* __restrict__ As,
                                           const float* __restrict__ Bs,
                                           float acc[2][8][4], int m0, int g, int tig)
{
#pragma unroll
    for (int ks = 0; ks < 4; ks++) {
        const int k = ks * 8;
        uint32_t a[2][4];
#pragma unroll
        for (int mf = 0; mf < 2; mf++) {
            const float* ap = As + (k + tig) * KMS + m0 + mf * 16 + g;
            a[mf][0] = __float_as_uint(ap[0]);
            a[mf][1] = __float_as_uint(ap[8]);
            a[mf][2] = __float_as_uint(ap[4 * KMS]);
            a[mf][3] = __float_as_uint(ap[4 * KMS + 8]);
        }
#pragma unroll
        for (int nf = 0; nf < 8; nf++) {
            uint32_t b[2];
            const float* bp = Bs + (nf * 8 + g) * MKS + k + tig;
            b[0] = __float_as_uint(bp[0]);
            b[1] = __float_as_uint(bp[4]);
            MMA(acc[0][nf], a[0], b);
            MMA(acc[1][nf], a[1], b);
        }
    }
}

// ---------------------------------------------------------------------------
// Stage 1: QKV.  D[tv=128, d=64] = x^T[tv,c] @ w[d,c]^T, K=192.
// grid (tv_tile=50, part*3+nt=9, n=32), 128 threads.
// ---------------------------------------------------------------------------
__global__ __launch_bounds__(128) void k1(const float* __restrict__ x,
                                          const float* __restrict__ w_in,
                                          const float* __restrict__ b_in)
{
    __shared__ float As[32 * KMS];   // [k=c][m=tv]
    __shared__ float Bs[64 * MKS];   // [n=d][k=c]

    const int tid = threadIdx.x, wid = tid >> 5, lane = tid & 31;
    const int g = lane >> 2, tig = lane & 3, m0 = wid * 32;
    const int n = blockIdx.z, part = blockIdx.y / 3, nt = blockIdx.y % 3;
    const int tv0 = blockIdx.x * 128;

    float acc[2][8][4] = {};

    for (int kc = 0; kc < 6; kc++) {
        __syncthreads();
        // A: x transpose chunk: 8 passes of float4
#pragma unroll
        for (int p = 0; p < 8; p++) {
            int c = p * 4 + (tid >> 5);
            int t4 = (tid & 31) * 4;
            float4 v = *(const float4*)&x[((size_t)n * C_ + kc * 32 + c) * TV_ + tv0 + t4];
            *(float4*)&As[c * KMS + t4] = tf32x4(v);
        }
        // B: w_in rows (d), contiguous in c
#pragma unroll
        for (int j = 0; j < 4; j++) {
            int r = tid >> 1, q = (tid & 1) * 16 + j * 4;
            float4 v = *(const float4*)&w_in[(part * C_ + nt * 64 + r) * C_ + kc * 32 + q];
            *(float4*)&Bs[r * MKS + q] = tf32x4(v);
        }
        __syncthreads();
        compute_km(As, Bs, acc, m0, g, tig);
    }

    const int ns = n * 3 + nt;
#pragma unroll
    for (int mf = 0; mf < 2; mf++) {
#pragma unroll
        for (int half = 0; half < 2; half++) {
            const int r = m0 + mf * 16 + half * 8 + g;
            const int tv = tv0 + r, t = tv / 25, v = tv % 25;
#pragma unroll
            for (int nf = 0; nf < 8; nf++) {
                const int cl = nf * 8 + 2 * tig;
                float2 o;
                o.x = acc[mf][nf][half * 2 + 0] + __ldg(&b_in[part * C_ + nt * 64 + cl]);
                o.y = acc[mf][nf][half * 2 + 1] + __ldg(&b_in[part * C_ + nt * 64 + cl + 1]);
                if (part == 0) {
                    *(float2*)&g_qt[((size_t)ns * T_ + t) * KQK_ + v * 64 + cl] = o;
                } else if (part == 1) {
                    *(float2*)&g_kt[((size_t)ns * T_ + t) * KQK_ + v * 64 + cl] = o;
                } else {
                    g_vt[((size_t)ns * KQK_ + v * 64 + cl) * T_ + t] = o.x;
                    g_vt[((size_t)ns * KQK_ + v * 64 + cl + 1) * T_ + t] = o.y;
                }
            }
        }
    }
}

// ---------------------------------------------------------------------------
// Stage 2: att = tanh(Q K^T / 1600).  D[t=128, q=64], K=1600.
// grid (qtile=4, ttile=2, ns=96)
// ---------------------------------------------------------------------------
__global__ __launch_bounds__(128) void k2()
{
    __shared__ float As[128 * MKS];  // [t][k]
    __shared__ float Bs[64 * MKS];   // [q][k]

    const int tid = threadIdx.x, wid = tid >> 5, lane = tid & 31;
    const int g = lane >> 2, tig = lane & 3, m0 = wid * 32;
    const int ns = blockIdx.z, t0 = blockIdx.y * 128, q0 = blockIdx.x * 64;

    float acc[2][8][4] = {};

    for (int kc = 0; kc < 50; kc++) {
        __syncthreads();
#pragma unroll
        for (int i = 0; i < 8; i++) {
            int r = i * 16 + (tid >> 3), q = (tid & 7) * 4;
            float4 v = *(const float4*)&g_qt[((size_t)ns * T_ + t0 + r) * KQK_ + kc * 32 + q];
            *(float4*)&As[r * MKS + q] = tf32x4(v);
        }
#pragma unroll
        for (int i = 0; i < 4; i++) {
            int r = i * 16 + (tid >> 3), q = (tid & 7) * 4;
            float4 v = *(const float4*)&g_kt[((size_t)ns * T_ + q0 + r) * KQK_ + kc * 32 + q];
            *(float4*)&Bs[r * MKS + q] = tf32x4(v);
        }
        __syncthreads();
        compute_mk(As, Bs, acc, m0, g, tig);
    }

#pragma unroll
    for (int mf = 0; mf < 2; mf++) {
#pragma unroll
        for (int half = 0; half < 2; half++) {
            const int t = t0 + m0 + mf * 16 + half * 8 + g;
            float* row = &g_att[((size_t)ns * T_ + t) * T_ + q0];
#pragma unroll
            for (int nf = 0; nf < 8; nf++) {
                const int cl = nf * 8 + 2 * tig;
                float2 o;
                o.x = tanhf(acc[mf][nf][half * 2 + 0] * (1.0f / 1600.0f));
                o.y = tanhf(acc[mf][nf][half * 2 + 1] * (1.0f / 1600.0f));
                *(float2*)&row[cl] = o;
            }
        }
    }
}

// ---------------------------------------------------------------------------
// Stage 3: Y = att @ V.  D[t=128, c=64] for fixed v=jv, K=256.
// grid (jv=25, ttile=2, ns=96)
// ---------------------------------------------------------------------------
__global__ __launch_bounds__(128) void k3()
{
    __shared__ float As[128 * MKS];  // [t][k=q]
    __shared__ float Bs[64 * MKS];   // [c][k=q]

    const int tid = threadIdx.x, wid = tid >> 5, lane = tid & 31;
    const int g = lane >> 2, tig = lane & 3, m0 = wid * 32;
    const int ns = blockIdx.z, t0 = blockIdx.y * 128, jv = blockIdx.x;
    const int n = ns / 3, s = ns % 3;

    float acc[2][8][4] = {};

    for (int kc = 0; kc < 8; kc++) {
        __syncthreads();
#pragma unroll
        for (int i = 0; i < 8; i++) {
            int r = i * 16 + (tid >> 3), q = (tid & 7) * 4;
            float4 v = *(const float4*)&g_att[((size_t)ns * T_ + t0 + r) * T_ + kc * 32 + q];
            *(float4*)&As[r * MKS + q] = tf32x4(v);
        }
#pragma unroll
        for (int i = 0; i < 4; i++) {
            int r = i * 16 + (tid >> 3), q = (tid & 7) * 4;
            float4 v = *(const float4*)&g_vt[((size_t)ns * KQK_ + jv * 64 + r) * T_ + kc * 32 + q];
            *(float4*)&Bs[r * MKS + q] = tf32x4(v);
        }
        __syncthreads();
        compute_mk(As, Bs, acc, m0, g, tig);
    }

#pragma unroll
    for (int mf = 0; mf < 2; mf++) {
#pragma unroll
        for (int half = 0; half < 2; half++) {
            const int t = t0 + m0 + mf * 16 + half * 8 + g;
            float* base = &g_y[((size_t)n * TV_ + (size_t)t * 25 + jv) * C_ + s * 64];
#pragma unroll
            for (int nf = 0; nf < 8; nf++) {
                const int cl = nf * 8 + 2 * tig;
                float2 o;
                o.x = acc[mf][nf][half * 2 + 0];
                o.y = acc[mf][nf][half * 2 + 1];
                *(float2*)&base[cl] = o;
            }
        }
    }
}

// ---------------------------------------------------------------------------
// Stage 4: FF + BN + residual + LeakyReLU.  D[tv=128, d=64], K=192.
// grid (tv_tile=50, nt=3, n=32)
// ---------------------------------------------------------------------------
__global__ __launch_bounds__(128) void k4(const float* __restrict__ x,
                                          const float* __restrict__ w_ff,
                                          const float* __restrict__ b_ff,
                                          const float* __restrict__ bn_gamma,
                                          const float* __restrict__ bn_beta,
                                          const float* __restrict__ bn_mean,
                                          const float* __restrict__ bn_var,
                                          float* __restrict__ out)
{
    __shared__ float As[128 * MKS];  // [tv][k=c]
    __shared__ float Bs[64 * MKS];   // [d][k=c]

    const int tid = threadIdx.x, wid = tid >> 5, lane = tid & 31;
    const int g = lane >> 2, tig = lane & 3, m0 = wid * 32;
    const int n = blockIdx.z, nt = blockIdx.y, tv0 = blockIdx.x * 128;

    float acc[2][8][4] = {};

    for (int kc = 0; kc < 6; kc++) {
        __syncthreads();
#pragma unroll
        for (int i = 0; i < 8; i++) {
            int r = i * 16 + (tid >> 3), q = (tid & 7) * 4;
            float4 v = *(const float4*)&g_y[((size_t)n * TV_ + tv0 + r) * C_ + kc * 32 + q];
            *(float4*)&As[r * MKS + q] = tf32x4(v);
        }
#pragma unroll
        for (int i = 0; i < 4; i++) {
            int r = i * 16 + (tid >> 3), q = (tid & 7) * 4;
            float4 v = *(const float4*)&w_ff[(nt * 64 + r) * C_ + kc * 32 + q];
            *(float4*)&Bs[r * MKS + q] = tf32x4(v);
        }
        __syncthreads();
        compute_mk(As, Bs, acc, m0, g, tig);
    }

#pragma unroll
    for (int nf = 0; nf < 8; nf++) {
#pragma unroll
        for (int p = 0; p < 2; p++) {
            const int d = nt * 64 + nf * 8 + 2 * tig + p;
            const float inv  = __ldg(&bn_gamma[d]) * rsqrtf(__ldg(&bn_var[d]) + 1e-5f);
            const float mean = __ldg(&bn_mean[d]);
            const float beta = __ldg(&bn_beta[d]);
            const float bias = __ldg(&b_ff[d]);
            const float* xr = &x[((size_t)n * C_ + d) * TV_ + tv0];
            float* orow = &out[((size_t)n * C_ + d) * TV_ + tv0];
#pragma unroll
            for (int mf = 0; mf < 2; mf++) {
#pragma unroll
                for (int half = 0; half < 2; half++) {
                    const int r = m0 + mf * 16 + half * 8 + g;
                    float o = acc[mf][nf][half * 2 + p] + bias;
                    o = (o - mean) * inv + beta;
                    float z = xr[r] + o;
                    orow[r] = (z >= 0.0f) ? z : 0.1f * z;
                }
            }
        }
    }
}

// ---------------------------------------------------------------------------
extern "C" void kernel_launch(void* const* d_in, const int* in_sizes, int n_in,
                              void* d_out, int out_size)
{
    const float* x        = (const float*)d_in[0];
    const float* w_in     = (const float*)d_in[1];
    const float* b_in     = (const float*)d_in[2];
    const float* w_ff     = (const float*)d_in[3];
    const float* b_ff     = (const float*)d_in[4];
    const float* bn_gamma = (const float*)d_in[5];
    const float* bn_beta  = (const float*)d_in[6];
    const float* bn_mean  = (const float*)d_in[7];
    const float* bn_var   = (const float*)d_in[8];
    float* out = (float*)d_out;

    k1<<<dim3(50, 9, 32), 128>>>(x, w_in, b_in);
    k2<<<dim3(4, 2, 96), 128>>>();
    k3<<<dim3(25, 2, 96), 128>>>();
    k4<<<dim3(50, 3, 32), 128>>>(x, w_ff, b_ff, bn_gamma, bn_beta,
                                 bn_mean, bn_var, out);
}